// round 1
// baseline (speedup 1.0000x reference)
#include <cuda_runtime.h>
#include <cstdint>

// Embedding gather: out[i, :] = w[x[i], :]
// x: [N=16384] int32, w: [32000, 1024] f32, out: [N, 1024] f32.
// DIM = 1024 floats = 256 float4 per row.
//
// Layout: 256 threads per block, ROWS_PER_BLOCK rows per block.
// Each thread moves ROWS_PER_BLOCK float4's (one per row), fully coalesced.

#define DIM 1024
#define VECS_PER_ROW (DIM / 4)      // 256 float4 per row
#define THREADS 256
#define ROWS_PER_BLOCK 4

__global__ __launch_bounds__(THREADS)
void embed_gather_kernel(const int* __restrict__ x,
                         const float4* __restrict__ w,
                         float4* __restrict__ out,
                         int n_rows)
{
    const int tid = threadIdx.x;              // 0..255 == vec index within row
    const int row0 = blockIdx.x * ROWS_PER_BLOCK;

    // Load the indices for this block's rows first (independent scalar loads),
    // then issue all ROWS_PER_BLOCK gather loads back-to-back for MLP.
    int idx[ROWS_PER_BLOCK];
#pragma unroll
    for (int r = 0; r < ROWS_PER_BLOCK; r++) {
        int row = row0 + r;
        idx[r] = (row < n_rows) ? x[row] : 0;
    }

    float4 v[ROWS_PER_BLOCK];
#pragma unroll
    for (int r = 0; r < ROWS_PER_BLOCK; r++) {
        v[r] = w[(size_t)idx[r] * VECS_PER_ROW + tid];
    }

#pragma unroll
    for (int r = 0; r < ROWS_PER_BLOCK; r++) {
        int row = row0 + r;
        if (row < n_rows) {
            out[(size_t)row * VECS_PER_ROW + tid] = v[r];
        }
    }
}

extern "C" void kernel_launch(void* const* d_in, const int* in_sizes, int n_in,
                              void* d_out, int out_size)
{
    // metadata order: x (int32, B*S = 16384), w (float32, 32000*1024)
    const int* x = (const int*)d_in[0];
    const float4* w = (const float4*)d_in[1];
    float4* out = (float4*)d_out;

    const int n_rows = in_sizes[0];           // 16384
    const int grid = (n_rows + ROWS_PER_BLOCK - 1) / ROWS_PER_BLOCK;

    embed_gather_kernel<<<grid, THREADS>>>(x, w, out, n_rows);
}

// round 2
// speedup vs baseline: 1.2239x; 1.2239x over previous
#include <cuda_runtime.h>
#include <cstdint>

// Embedding gather: out[i, :] = w[x[i], :]
// x: [N=16384] int32, w: [32000, 1024] f32, out: [N, 1024] f32.
//
// R2 changes vs R1:
//  - ROWS_PER_BLOCK 4 -> 8 : more per-thread MLP to cover L2 latency
//    (reads are mostly L2-hits; 234-262 cyc latency was exposed).
//  - __stcs streaming stores: output is write-once streaming traffic; mark
//    evict-first in L2 so the 128MB w table stays L2-resident across replays.

#define DIM 1024
#define VECS_PER_ROW (DIM / 4)      // 256 float4 per row
#define THREADS 256
#define ROWS_PER_BLOCK 8

__global__ __launch_bounds__(THREADS)
void embed_gather_kernel(const int* __restrict__ x,
                         const float4* __restrict__ w,
                         float4* __restrict__ out,
                         int n_rows)
{
    const int tid = threadIdx.x;              // 0..255 == vec index within row
    const int row0 = blockIdx.x * ROWS_PER_BLOCK;

    // Indices first (uniform broadcast loads), then all gather loads
    // back-to-back for maximum memory-level parallelism.
    int idx[ROWS_PER_BLOCK];
#pragma unroll
    for (int r = 0; r < ROWS_PER_BLOCK; r++) {
        int row = row0 + r;
        idx[r] = (row < n_rows) ? __ldg(&x[row]) : 0;
    }

    float4 v[ROWS_PER_BLOCK];
#pragma unroll
    for (int r = 0; r < ROWS_PER_BLOCK; r++) {
        v[r] = __ldg(&w[(size_t)idx[r] * VECS_PER_ROW + tid]);
    }

#pragma unroll
    for (int r = 0; r < ROWS_PER_BLOCK; r++) {
        int row = row0 + r;
        if (row < n_rows) {
            // Streaming (evict-first) store: don't displace w from L2.
            __stcs(&out[(size_t)row * VECS_PER_ROW + tid], v[r]);
        }
    }
}

extern "C" void kernel_launch(void* const* d_in, const int* in_sizes, int n_in,
                              void* d_out, int out_size)
{
    // metadata order: x (int32, B*S = 16384), w (float32, 32000*1024)
    const int* x = (const int*)d_in[0];
    const float4* w = (const float4*)d_in[1];
    float4* out = (float4*)d_out;

    const int n_rows = in_sizes[0];           // 16384
    const int grid = (n_rows + ROWS_PER_BLOCK - 1) / ROWS_PER_BLOCK;

    embed_gather_kernel<<<grid, THREADS>>>(x, w, out, n_rows);
}

// round 3
// speedup vs baseline: 1.2448x; 1.0171x over previous
#include <cuda_runtime.h>
#include <cstdint>

// Embedding gather: out[i, :] = w[x[i], :]
// x: [N=16384] int32, w: [32000, 1024] f32, out: [N, 1024] f32.
//
// R2 changes vs R1:
//  - ROWS_PER_BLOCK 4 -> 8 : more per-thread MLP to cover L2 latency
//    (reads are mostly L2-hits; 234-262 cyc latency was exposed).
//  - __stcs streaming stores: output is write-once streaming traffic; mark
//    evict-first in L2 so the 128MB w table stays L2-resident across replays.

#define DIM 1024
#define VECS_PER_ROW (DIM / 4)      // 256 float4 per row
#define THREADS 256
#define ROWS_PER_BLOCK 8

__global__ __launch_bounds__(THREADS)
void embed_gather_kernel(const int* __restrict__ x,
                         const float4* __restrict__ w,
                         float4* __restrict__ out,
                         int n_rows)
{
    const int tid = threadIdx.x;              // 0..255 == vec index within row
    const int row0 = blockIdx.x * ROWS_PER_BLOCK;

    // Indices first (uniform broadcast loads), then all gather loads
    // back-to-back for maximum memory-level parallelism.
    int idx[ROWS_PER_BLOCK];
#pragma unroll
    for (int r = 0; r < ROWS_PER_BLOCK; r++) {
        int row = row0 + r;
        idx[r] = (row < n_rows) ? __ldg(&x[row]) : 0;
    }

    float4 v[ROWS_PER_BLOCK];
#pragma unroll
    for (int r = 0; r < ROWS_PER_BLOCK; r++) {
        v[r] = __ldg(&w[(size_t)idx[r] * VECS_PER_ROW + tid]);
    }

#pragma unroll
    for (int r = 0; r < ROWS_PER_BLOCK; r++) {
        int row = row0 + r;
        if (row < n_rows) {
            // Streaming (evict-first) store: don't displace w from L2.
            __stcs(&out[(size_t)row * VECS_PER_ROW + tid], v[r]);
        }
    }
}

extern "C" void kernel_launch(void* const* d_in, const int* in_sizes, int n_in,
                              void* d_out, int out_size)
{
    // metadata order: x (int32, B*S = 16384), w (float32, 32000*1024)
    const int* x = (const int*)d_in[0];
    const float4* w = (const float4*)d_in[1];
    float4* out = (float4*)d_out;

    const int n_rows = in_sizes[0];           // 16384
    const int grid = (n_rows + ROWS_PER_BLOCK - 1) / ROWS_PER_BLOCK;

    embed_gather_kernel<<<grid, THREADS>>>(x, w, out, n_rows);
}